// round 7
// baseline (speedup 1.0000x reference)
#include <cuda_runtime.h>
#include <stdint.h>
#include <math.h>

// DistanceTransformLoss, fused single kernel.
// out = mean(BCEWithLogits(pred,tgt)) + sqrt( sum(pred_bin*dist)/max(cnt,1) ), 0 if sum==0
// dist[h] = min(|h - nearest target along H|, H) per (n,w) column. Shapes (32,1,1024,1024) f32.
//
// Block = 128-column x full-H tile, 512 threads, 256 blocks.
// Pass 1: 3-stage cp.async pipeline stages 32-row x 128-col chunks of preds+targs
//   into smem (2 chunks = 64KB/SM always in flight -> HBM-saturating regardless of
//   register allocation). Threads compute BCE from smem and emit per-(col,8-row)
//   mask bytes into padded per-column bit arrays.
// Pass 2: each thread resolves the distance transform for a 256-row segment of one
//   column from the 1024-bit masks (conflict-free padded layout).
// Finisher fused via atomic ticket; integer partials -> deterministic.

#define NTHREADS 512
#define NBLOCKS  256           // 32 n * (1024/128) w-tiles
#define HH 1024
#define WW 1024
#define NCHUNKS 32             // 1024 rows / 32-row chunks
#define NSTAGES 3
#define TILE_W 128
#define NWORDS 32              // 1024 bits per column
#define MASK_STRIDE 33         // padded words per column (coprime 32 -> conflict-free)
#define BIG (1 << 20)

#define STAGE_STRIDE 32768               // 16KB preds + 16KB targs per stage
#define STAGES_BYTES (NSTAGES * STAGE_STRIDE)
#define MASK_BYTES   (TILE_W * MASK_STRIDE * 4)
#define MASK_T_OFF   STAGES_BYTES
#define MASK_P_OFF   (MASK_T_OFF + MASK_BYTES)
#define DYN_TOTAL    (MASK_P_OFF + MASK_BYTES)   // 98304 + 2*16896 = 132096 B

__device__ double       g_part_bce[NBLOCKS];
__device__ unsigned int g_part_tot[NBLOCKS];
__device__ unsigned int g_part_cnt[NBLOCKS];
__device__ unsigned int g_counter;   // zero-init; reset by electing block each run

__device__ __forceinline__ float bce_term(float p, float t) {
    return fmaxf(p, 0.f) - p * t + __logf(1.f + __expf(-fabsf(p)));
}
__device__ __forceinline__ void cp16(uint32_t dst, const void* src) {
    asm volatile("cp.async.cg.shared.global [%0], [%1], 16;" :: "r"(dst), "l"(src));
}

extern __shared__ char dynsmem[];

__global__ void __launch_bounds__(NTHREADS)
dtl_fused(const float* __restrict__ preds, const float* __restrict__ targs,
          float* __restrict__ out) {
    const int tid = threadIdx.x;
    const int n   = blockIdx.x >> 3;          // 8 w-tiles per n
    const int w0  = (blockIdx.x & 7) << 7;    // *128

    const char* gp = (const char*)(preds + (long)n * (HH * WW) + w0);
    const char* gt = (const char*)(targs + (long)n * (HH * WW) + w0);
    const uint32_t smem0 = (uint32_t)__cvta_generic_to_shared(dynsmem);

    // copy mapping: thread t copies 16B segs of chunk-rows r0 and r0+16
    const int r0  = tid >> 5;                 // 0..15
    const int seg = (tid & 31) << 4;          // byte offset within 512B row

    // ---- prologue: fill stages 0..2 ----
    #pragma unroll
    for (int s = 0; s < NSTAGES; ++s) {
        const long grow = (long)(s * 32 + r0) * (WW * 4) + seg;
        const uint32_t sb = smem0 + s * STAGE_STRIDE;
        cp16(sb + r0 * 512 + seg,                gp + grow);
        cp16(sb + (r0 + 16) * 512 + seg,         gp + grow + 16L * WW * 4);
        cp16(sb + 16384 + r0 * 512 + seg,        gt + grow);
        cp16(sb + 16384 + (r0 + 16) * 512 + seg, gt + grow + 16L * WW * 4);
        asm volatile("cp.async.commit_group;");
    }

    // compute mapping: thread owns col (tid&127), row-octet q (tid>>7) per chunk
    const int col = tid & 127;
    const int q   = tid >> 7;                 // 0..3
    uint8_t* const mt = (uint8_t*)(dynsmem + MASK_T_OFF) + col * (MASK_STRIDE * 4);
    uint8_t* const mp = (uint8_t*)(dynsmem + MASK_P_OFF) + col * (MASK_STRIDE * 4);

    float bce = 0.f;

    for (int c = 0; c < NCHUNKS; ++c) {
        if (c < NCHUNKS - 2)       asm volatile("cp.async.wait_group %0;" :: "n"(NSTAGES - 1));
        else if (c == NCHUNKS - 2) asm volatile("cp.async.wait_group 1;");
        else                       asm volatile("cp.async.wait_group 0;");
        __syncthreads();

        const int s = c % NSTAGES;
        const float* sp = (const float*)(dynsmem + s * STAGE_STRIDE);
        const float* st = (const float*)(dynsmem + s * STAGE_STRIDE + 16384);

        uint32_t tb = 0u, pb = 0u;
        #pragma unroll
        for (int b = 0; b < 8; ++b) {
            const int rl = (q << 3) + b;
            float p = sp[rl * TILE_W + col];
            float t = st[rl * TILE_W + col];
            bce += bce_term(p, t);
            if (t > 0.5f) tb |= (1u << b);
            if (p > 0.0f) pb |= (1u << b);   // sigmoid(p)>0.5 <=> p>0
        }
        mt[(c << 2) + q] = (uint8_t)tb;
        mp[(c << 2) + q] = (uint8_t)pb;
        __syncthreads();

        const int cn = c + NSTAGES;
        if (cn < NCHUNKS) {
            const long grow = (long)(cn * 32 + r0) * (WW * 4) + seg;
            const uint32_t sb = smem0 + s * STAGE_STRIDE;
            cp16(sb + r0 * 512 + seg,                gp + grow);
            cp16(sb + (r0 + 16) * 512 + seg,         gp + grow + 16L * WW * 4);
            cp16(sb + 16384 + r0 * 512 + seg,        gt + grow);
            cp16(sb + 16384 + (r0 + 16) * 512 + seg, gt + grow + 16L * WW * 4);
            asm volatile("cp.async.commit_group;");
        }
    }
    __syncthreads();   // all mask bytes visible

    // ---- Pass 2: distance transform, 256-row segment of own column ----
    const uint32_t* twv = (const uint32_t*)(dynsmem + MASK_T_OFF) + col * MASK_STRIDE;
    const uint32_t* pwv = (const uint32_t*)(dynsmem + MASK_P_OFF) + col * MASK_STRIDE;
    const int wbase = q << 3;                 // 8 words per segment

    int lt = -BIG;
    for (int w = wbase - 1; w >= 0; --w) {
        uint32_t v = twv[w];
        if (v) { lt = (w << 5) + 31 - __clz(v); break; }
    }
    int scanw = wbase;
    uint32_t curm = twv[scanw];
    int nt;
    while (curm == 0u && scanw < NWORDS - 1) { ++scanw; curm = twv[scanw]; }
    if (curm) { nt = (scanw << 5) + __ffs(curm) - 1; curm &= curm - 1u; }
    else        nt = BIG;

    uint32_t tot = 0u, cnt = 0u;
    #pragma unroll
    for (int wo = 0; wo < 8; ++wo) {
        const uint32_t tw = twv[wbase + wo];
        const uint32_t pw = pwv[wbase + wo];
        const int hbase = (wbase + wo) << 5;
        #pragma unroll 4
        for (int b = 0; b < 32; ++b) {
            int h = hbase + b;
            if ((tw >> b) & 1u) {
                lt = h;
                while (curm == 0u && scanw < NWORDS - 1) { ++scanw; curm = twv[scanw]; }
                if (curm) { nt = (scanw << 5) + __ffs(curm) - 1; curm &= curm - 1u; }
                else        nt = BIG;
            } else if ((pw >> b) & 1u) {
                tot += (uint32_t)min(min(h - lt, nt - h), HH);
                cnt += 1u;
            }
        }
    }

    // ---- Block reduction -> fixed per-block slots ----
    const unsigned fullm = 0xFFFFFFFFu;
    for (int off = 16; off; off >>= 1) {
        bce += __shfl_down_sync(fullm, bce, off);
        tot += __shfl_down_sync(fullm, tot, off);
        cnt += __shfl_down_sync(fullm, cnt, off);
    }
    __shared__ float    rb[16];
    __shared__ uint32_t rt[16], rc[16];
    const int wid = tid >> 5, lane = tid & 31;
    if (lane == 0) { rb[wid] = bce; rt[wid] = tot; rc[wid] = cnt; }
    __syncthreads();
    __shared__ int s_last;
    if (tid == 0) {
        float    b2 = 0.f;
        uint32_t t2 = 0u, c2 = 0u;
        #pragma unroll
        for (int i = 0; i < 16; ++i) { b2 += rb[i]; t2 += rt[i]; c2 += rc[i]; }
        g_part_bce[blockIdx.x] = (double)b2;
        g_part_tot[blockIdx.x] = t2;
        g_part_cnt[blockIdx.x] = c2;
        __threadfence();
        unsigned old = atomicAdd(&g_counter, 1u);
        s_last = (old == NBLOCKS - 1);
    }
    __syncthreads();

    // ---- Last block: deterministic final reduction + scalar write ----
    if (s_last) {
        __shared__ double             fb[NBLOCKS];
        __shared__ unsigned long long ft[NBLOCKS], fc[NBLOCKS];
        if (tid < NBLOCKS) {
            fb[tid] = g_part_bce[tid];
            ft[tid] = (unsigned long long)g_part_tot[tid];
            fc[tid] = (unsigned long long)g_part_cnt[tid];
        }
        __syncthreads();
        for (int s = NBLOCKS / 2; s; s >>= 1) {
            if (tid < s) { fb[tid] += fb[tid + s]; ft[tid] += ft[tid + s]; fc[tid] += fc[tid + s]; }
            __syncthreads();
        }
        if (tid == 0) {
            double bce_mean = fb[0] / 33554432.0;    // 32*1024*1024
            double totd = (double)ft[0];
            double cntd = (double)fc[0];
            double border = (ft[0] == 0ull) ? 0.0 : totd / (cntd < 1.0 ? 1.0 : cntd);
            out[0] = (float)(bce_mean + sqrt(border));
            g_counter = 0u;                          // reset for next replay
        }
    }
}

extern "C" void kernel_launch(void* const* d_in, const int* in_sizes, int n_in,
                              void* d_out, int out_size) {
    const float* preds = (const float*)d_in[0];
    const float* targs = (const float*)d_in[1];
    cudaFuncSetAttribute(dtl_fused, cudaFuncAttributeMaxDynamicSharedMemorySize, DYN_TOTAL);
    dtl_fused<<<NBLOCKS, NTHREADS, DYN_TOTAL>>>(preds, targs, (float*)d_out);
}

// round 11
// speedup vs baseline: 1.2239x; 1.2239x over previous
#include <cuda_runtime.h>
#include <stdint.h>
#include <math.h>

// DistanceTransformLoss v2c (two-kernel split; fixes tbit: use mantissa-MSB/
// exponent bit 23, which is 1 for 1.0f and 0 for 0.0f — bit 30 is NOT set in 1.0f).
//
// out = mean(BCEWithLogits(pred,tgt)) + sqrt( sum(pred_bin*dist)/max(cnt,1) ), 0 if sum==0
// dist[h] = min(|h - nearest target along H|, H) per (n,w) column. Shapes (32,1,1024,1024) f32.
//
// Kernel A (dtl_stream2): pure streamer. 262144 threads; thread = 32 rows x 4 cols
//   (float4 loads). BCE partials per block; target/pred-sign mask words to global
//   scratch (maskT/maskP, 4MB each, layout [n][R][w], R = 32-row word index).
// Kernel B (dtl_dist2): distance transform from masks. Thread = 256-row segment of
//   one column. Integer tot/cnt via atomics (order-independent => deterministic);
//   ticketed last block folds A's BCE partials in fixed order, writes scalar,
//   resets accumulators for graph replay.

#define A_BLOCKS 1024
#define B_BLOCKS 512
#define NT 256
#define HH 1024
#define WW 1024
#define BIG (1 << 20)

__device__ uint32_t g_maskT[32 * 32 * 1024];   // [n][R][w], 4MB
__device__ uint32_t g_maskP[32 * 32 * 1024];
__device__ double   g_part_bce[A_BLOCKS];
__device__ unsigned long long g_tot, g_cnt;    // zero-init; reset by finisher
__device__ unsigned int g_counter;             // zero-init; reset by finisher

__device__ __forceinline__ float bce_term(float p, float t) {
    // max(p,0) - p*t + log1p(exp(-|p|))
    return fmaxf(p, 0.f) - p * t + __logf(1.f + __expf(-fabsf(p)));
}
// t in {0.0f, 1.0f}: bit 23 of the IEEE encoding is 1 for 1.0f (exp=127) and 0 for 0.0f.
__device__ __forceinline__ uint32_t tbit(float t) {
    return (__float_as_uint(t) >> 23) & 1u;
}
// p > 0  <=>  signed-int bit pattern > 0 (handles sign bit; +0 excluded correctly).
__device__ __forceinline__ uint32_t pbit(float p) {
    return (uint32_t)((int)__float_as_uint(p) > 0);
}
__device__ __forceinline__ int mask_index(int n, int R, int w) {
    return (((n << 5) + R) << 10) + w;
}

__global__ void __launch_bounds__(NT)
dtl_stream2(const float* __restrict__ preds, const float* __restrict__ targs) {
    const int tid = blockIdx.x * NT + threadIdx.x;
    const int c4 = tid & 255;            // 4-column group: cols 4*c4..4*c4+3
    const int R  = (tid >> 8) & 31;      // 32-row word index
    const int n  = tid >> 13;

    const long base = ((long)n << 20) + ((long)(R << 5) << 10) + (c4 << 2);
    const float* pb = preds + base;
    const float* tb = targs + base;

    uint32_t tw0 = 0, tw1 = 0, tw2 = 0, tw3 = 0;
    uint32_t pw0 = 0, pw1 = 0, pw2 = 0, pw3 = 0;
    float bce = 0.f;

    #pragma unroll
    for (int j8 = 0; j8 < 8; ++j8) {
        float4 P[4], T[4];
        #pragma unroll
        for (int k = 0; k < 4; ++k) {
            P[k] = __ldcs((const float4*)(pb + (((j8 << 2) + k) << 10)));
            T[k] = __ldcs((const float4*)(tb + (((j8 << 2) + k) << 10)));
        }
        #pragma unroll
        for (int k = 0; k < 4; ++k) {
            const int j = (j8 << 2) + k;
            bce += bce_term(P[k].x, T[k].x) + bce_term(P[k].y, T[k].y)
                 + bce_term(P[k].z, T[k].z) + bce_term(P[k].w, T[k].w);
            tw0 |= tbit(T[k].x) << j;  pw0 |= pbit(P[k].x) << j;
            tw1 |= tbit(T[k].y) << j;  pw1 |= pbit(P[k].y) << j;
            tw2 |= tbit(T[k].z) << j;  pw2 |= pbit(P[k].z) << j;
            tw3 |= tbit(T[k].w) << j;  pw3 |= pbit(P[k].w) << j;
        }
    }

    // mask words out (coalesced uint4)
    const int midx = mask_index(n, R, c4 << 2);
    *(uint4*)(g_maskT + midx) = make_uint4(tw0, tw1, tw2, tw3);
    *(uint4*)(g_maskP + midx) = make_uint4(pw0, pw1, pw2, pw3);

    // deterministic per-block BCE partial
    const unsigned fullm = 0xFFFFFFFFu;
    for (int off = 16; off; off >>= 1) bce += __shfl_down_sync(fullm, bce, off);
    __shared__ float rb[8];
    const int wid = threadIdx.x >> 5, lane = threadIdx.x & 31;
    if (lane == 0) rb[wid] = bce;
    __syncthreads();
    if (threadIdx.x == 0) {
        float b2 = 0.f;
        #pragma unroll
        for (int i = 0; i < 8; ++i) b2 += rb[i];
        g_part_bce[blockIdx.x] = (double)b2;
    }
}

__global__ void __launch_bounds__(NT)
dtl_dist2(float* __restrict__ out) {
    const int tid  = blockIdx.x * NT + threadIdx.x;   // 0..131071
    const int q    = tid >> 15;                       // segment 0..3 (rows 256q..)
    const int colg = tid & 32767;
    const int n    = colg >> 10;
    const int w    = colg & 1023;

    const uint32_t* mt = g_maskT + mask_index(n, 0, w);  // word R at mt[R<<10]
    const uint32_t* mp = g_maskP + mask_index(n, 0, w);
    const int Rb = q << 3;                            // first of 8 words

    // lt: last target before segment
    int lt = -BIG;
    for (int R = Rb - 1; R >= 0; --R) {
        uint32_t v = mt[R << 10];
        if (v) { lt = (R << 5) + 31 - __clz(v); break; }
    }
    // nt iterator: next target >= segment start
    int scanw = Rb;
    uint32_t curm = mt[scanw << 10];
    int nt;
    while (curm == 0u && scanw < 31) { ++scanw; curm = mt[scanw << 10]; }
    if (curm) { nt = (scanw << 5) + __ffs(curm) - 1; curm &= curm - 1u; }
    else        nt = BIG;

    uint32_t tot = 0u, cnt = 0u;
    #pragma unroll
    for (int wo = 0; wo < 8; ++wo) {
        const uint32_t tw = mt[(Rb + wo) << 10];
        const uint32_t pw = mp[(Rb + wo) << 10];
        const int hbase = (Rb + wo) << 5;
        for (int b = 0; b < 32; ++b) {
            const int h = hbase + b;
            if ((tw >> b) & 1u) {
                lt = h;
                while (curm == 0u && scanw < 31) { ++scanw; curm = mt[scanw << 10]; }
                if (curm) { nt = (scanw << 5) + __ffs(curm) - 1; curm &= curm - 1u; }
                else        nt = BIG;
            } else if ((pw >> b) & 1u) {
                tot += (uint32_t)min(min(h - lt, nt - h), HH);
                cnt += 1u;
            }
        }
    }

    // integer warp+block reduce -> global atomics (order-independent)
    const unsigned fullm = 0xFFFFFFFFu;
    for (int off = 16; off; off >>= 1) {
        tot += __shfl_down_sync(fullm, tot, off);
        cnt += __shfl_down_sync(fullm, cnt, off);
    }
    __shared__ uint32_t rt[8], rc[8];
    const int wid = threadIdx.x >> 5, lane = threadIdx.x & 31;
    if (lane == 0) { rt[wid] = tot; rc[wid] = cnt; }
    __syncthreads();
    __shared__ int s_last;
    if (threadIdx.x == 0) {
        uint32_t t2 = 0u, c2 = 0u;
        #pragma unroll
        for (int i = 0; i < 8; ++i) { t2 += rt[i]; c2 += rc[i]; }
        atomicAdd(&g_tot, (unsigned long long)t2);
        atomicAdd(&g_cnt, (unsigned long long)c2);
        __threadfence();
        unsigned old = atomicAdd(&g_counter, 1u);
        s_last = (old == B_BLOCKS - 1);
    }
    __syncthreads();

    if (s_last) {
        // deterministic fold of A's 1024 BCE partials
        __shared__ double fb[NT];
        double b = 0.0;
        #pragma unroll
        for (int i = 0; i < A_BLOCKS / NT; ++i)
            b += g_part_bce[threadIdx.x + NT * i];
        fb[threadIdx.x] = b;
        __syncthreads();
        for (int s = NT / 2; s; s >>= 1) {
            if (threadIdx.x < s) fb[threadIdx.x] += fb[threadIdx.x + s];
            __syncthreads();
        }
        if (threadIdx.x == 0) {
            const unsigned long long T = g_tot, C = g_cnt;
            double bce_mean = fb[0] / 33554432.0;       // 32*1024*1024
            double border = (T == 0ull) ? 0.0
                           : (double)T / ((double)C < 1.0 ? 1.0 : (double)C);
            out[0] = (float)(bce_mean + sqrt(border));
            g_tot = 0ull; g_cnt = 0ull; g_counter = 0u;  // reset for next replay
        }
    }
}

extern "C" void kernel_launch(void* const* d_in, const int* in_sizes, int n_in,
                              void* d_out, int out_size) {
    const float* preds = (const float*)d_in[0];
    const float* targs = (const float*)d_in[1];
    dtl_stream2<<<A_BLOCKS, NT>>>(preds, targs);
    dtl_dist2<<<B_BLOCKS, NT>>>((float*)d_out);
}

// round 14
// speedup vs baseline: 1.7113x; 1.3983x over previous
#include <cuda_runtime.h>
#include <stdint.h>
#include <math.h>

// DistanceTransformLoss v3c (branchless word-parallel pass 2; third submission
// of the v3 design — cosmetic deltas only, broker has been flaky).
//
// out = mean(BCEWithLogits(pred,tgt)) + sqrt( sum(pred_bin*dist)/max(cnt,1) ), 0 if sum==0
// dist[h] = min(|h - nearest target along H|, H) per (n,w) column. Shapes (32,1,1024,1024) f32.
//
// Kernel A (stream_k): pure streamer (measured ~44us, near ~41us HBM floor).
//   Thread = 32 rows x 4 cols via float4; BCE + bitmask words to global scratch.
// Kernel B (dist_k): 1,048,576 threads; thread = one 32-bit word of one column.
//   lt/nt bootstrapped from neighbor words, then unrolled branchless 32-bit
//   loop (SEL/FFS/IMIN/IMAD + popc). Integer atomics + ticketed deterministic
//   finisher with accumulator reset for graph replay.

#define A_BLOCKS 1024
#define B_BLOCKS 4096
#define NT 256
#define HH 1024
#define MASK_WORDS (32 * 32 * 1024)

__device__ uint32_t g_maskT[MASK_WORDS];   // [n][R][w], 4MB
__device__ uint32_t g_maskP[MASK_WORDS];
__device__ double   g_part_bce[A_BLOCKS];
__device__ unsigned long long g_tot, g_cnt;    // zero-init; reset by finisher
__device__ unsigned int g_counter;             // zero-init; reset by finisher

__device__ __forceinline__ float bce_term(float p, float t) {
    return fmaxf(p, 0.f) - p * t + __logf(1.f + __expf(-fabsf(p)));
}
// t in {0.0f,1.0f}: IEEE bit 23 is 1 for 1.0f and 0 for 0.0f.
__device__ __forceinline__ uint32_t tb_of(float t) {
    return (__float_as_uint(t) >> 23) & 1u;
}
// p > 0 <=> signed-int bit pattern > 0.
__device__ __forceinline__ uint32_t pb_of(float p) {
    return (uint32_t)((int)__float_as_uint(p) > 0);
}

__global__ void __launch_bounds__(NT)
stream_k(const float* __restrict__ preds, const float* __restrict__ targs) {
    const int tid = blockIdx.x * NT + threadIdx.x;
    const int c4 = tid & 255;            // 4-column group
    const int R  = (tid >> 8) & 31;      // 32-row word index
    const int n  = tid >> 13;

    const long base = ((long)n << 20) + ((long)(R << 5) << 10) + (c4 << 2);
    const float* pb = preds + base;
    const float* tb = targs + base;

    uint32_t twx = 0, twy = 0, twz = 0, tww = 0;
    uint32_t pwx = 0, pwy = 0, pwz = 0, pww = 0;
    float bce = 0.f;

    #pragma unroll
    for (int j8 = 0; j8 < 8; ++j8) {
        float4 P[4], T[4];
        #pragma unroll
        for (int k = 0; k < 4; ++k) {
            P[k] = __ldcs((const float4*)(pb + (((j8 << 2) + k) << 10)));
            T[k] = __ldcs((const float4*)(tb + (((j8 << 2) + k) << 10)));
        }
        #pragma unroll
        for (int k = 0; k < 4; ++k) {
            const int j = (j8 << 2) + k;
            bce += bce_term(P[k].x, T[k].x) + bce_term(P[k].y, T[k].y)
                 + bce_term(P[k].z, T[k].z) + bce_term(P[k].w, T[k].w);
            twx |= tb_of(T[k].x) << j;  pwx |= pb_of(P[k].x) << j;
            twy |= tb_of(T[k].y) << j;  pwy |= pb_of(P[k].y) << j;
            twz |= tb_of(T[k].z) << j;  pwz |= pb_of(P[k].z) << j;
            tww |= tb_of(T[k].w) << j;  pww |= pb_of(P[k].w) << j;
        }
    }

    const int midx = (((n << 5) + R) << 10) + (c4 << 2);
    *(uint4*)(g_maskT + midx) = make_uint4(twx, twy, twz, tww);
    *(uint4*)(g_maskP + midx) = make_uint4(pwx, pwy, pwz, pww);

    const unsigned fm = 0xFFFFFFFFu;
    for (int off = 16; off; off >>= 1) bce += __shfl_down_sync(fm, bce, off);
    __shared__ float rb[8];
    const int wid = threadIdx.x >> 5, lane = threadIdx.x & 31;
    if (lane == 0) rb[wid] = bce;
    __syncthreads();
    if (threadIdx.x == 0) {
        float b2 = 0.f;
        #pragma unroll
        for (int i = 0; i < 8; ++i) b2 += rb[i];
        g_part_bce[blockIdx.x] = (double)b2;
    }
}

__global__ void __launch_bounds__(NT)
dist_k(float* __restrict__ out) {
    // blockIdx = ((n*32 + R) * 4 + wc); column w = wc*256 + threadIdx.x
    const int wc = blockIdx.x & 3;
    const int R  = (blockIdx.x >> 2) & 31;
    const int n  = blockIdx.x >> 7;
    const int w  = (wc << 8) + threadIdx.x;

    const uint32_t* mt = g_maskT + ((n << 15) + w);   // word r at mt[r<<10]
    const uint32_t tw = mt[R << 10];
    const uint32_t pq = g_maskP[(n << 15) + (R << 10) + w] & ~tw;

    // bootstrap: last target strictly before this word
    int ltv = -4096;
    for (int rr = R - 1; rr >= 0; --rr) {
        const uint32_t v = mt[rr << 10];
        if (v) { ltv = (rr << 5) + 31 - __clz(v); break; }
    }
    // bootstrap: first target strictly after this word
    int ntb = 8192;
    for (int rr = R + 1; rr < 32; ++rr) {
        const uint32_t v = mt[rr << 10];
        if (v) { ntb = (rr << 5) + __ffs(v) - 1; break; }
    }

    uint32_t tot = 0u;
    uint32_t cnt = (uint32_t)__popc(pq);
    const int h0 = R << 5;

    #pragma unroll
    for (int b = 0; b < 32; ++b) {
        const int h = h0 + b;
        const uint32_t mrem = tw >> b;                       // targets at/after h
        ltv = (mrem & 1u) ? h : ltv;                         // SEL
        const int ntv = mrem ? (h + __ffs(mrem) - 1) : ntb;  // SEL
        const int d = min(min(h - ltv, ntv - h), HH);
        tot += ((pq >> b) & 1u) * (uint32_t)d;               // IMAD
    }

    // integer warp+block reduce -> global atomics (order-independent)
    const unsigned fm = 0xFFFFFFFFu;
    for (int off = 16; off; off >>= 1) {
        tot += __shfl_down_sync(fm, tot, off);
        cnt += __shfl_down_sync(fm, cnt, off);
    }
    __shared__ uint32_t rt[8], rc[8];
    const int wid = threadIdx.x >> 5, lane = threadIdx.x & 31;
    if (lane == 0) { rt[wid] = tot; rc[wid] = cnt; }
    __syncthreads();
    __shared__ int s_last;
    if (threadIdx.x == 0) {
        uint32_t t2 = 0u, c2 = 0u;
        #pragma unroll
        for (int i = 0; i < 8; ++i) { t2 += rt[i]; c2 += rc[i]; }
        atomicAdd(&g_tot, (unsigned long long)t2);
        atomicAdd(&g_cnt, (unsigned long long)c2);
        __threadfence();
        const unsigned old = atomicAdd(&g_counter, 1u);
        s_last = (old == B_BLOCKS - 1);
    }
    __syncthreads();

    if (s_last) {
        __shared__ double fb[NT];
        double b = 0.0;
        #pragma unroll
        for (int i = 0; i < A_BLOCKS / NT; ++i)
            b += g_part_bce[threadIdx.x + NT * i];
        fb[threadIdx.x] = b;
        __syncthreads();
        for (int s = NT / 2; s; s >>= 1) {
            if (threadIdx.x < s) fb[threadIdx.x] += fb[threadIdx.x + s];
            __syncthreads();
        }
        if (threadIdx.x == 0) {
            const unsigned long long T = g_tot, C = g_cnt;
            const double bce_mean = fb[0] / 33554432.0;   // 32*1024*1024
            const double border = (T == 0ull) ? 0.0
                                 : (double)T / ((double)C < 1.0 ? 1.0 : (double)C);
            out[0] = (float)(bce_mean + sqrt(border));
            g_tot = 0ull; g_cnt = 0ull; g_counter = 0u;   // reset for next replay
        }
    }
}

extern "C" void kernel_launch(void* const* d_in, const int* in_sizes, int n_in,
                              void* d_out, int out_size) {
    const float* preds = (const float*)d_in[0];
    const float* targs = (const float*)d_in[1];
    stream_k<<<A_BLOCKS, NT>>>(preds, targs);
    dist_k<<<B_BLOCKS, NT>>>((float*)d_out);
}

// round 15
// speedup vs baseline: 1.7670x; 1.0325x over previous
#include <cuda_runtime.h>
#include <stdint.h>
#include <math.h>

// DistanceTransformLoss v4 (set-bit-iteration pass 2).
//
// out = mean(BCEWithLogits(pred,tgt)) + sqrt( sum(pred_bin*dist)/max(cnt,1) ), 0 if sum==0
// dist[h] = min(|h - nearest target along H|, H) per (n,w) column. Shapes (32,1,1024,1024) f32.
//
// Kernel A (stream_k): pure streamer (measured ~45.7us, near ~42us floor incl.
//   8MB mask writes). Thread = 32 rows x 4 cols via float4; BCE + bitmask words.
// Kernel B (dist_k): thread = one 32-bit word of one column. Iterates ONLY the
//   set bits of pq = predP & ~predT (~8/word): per bit, lt via CLZ of tw low
//   bits (else bootstrap), nt via FFS of tw high bits (else bootstrap) — no
//   loop-carried chain. Integer atomics + ticketed deterministic finisher.

#define A_BLOCKS 1024
#define B_BLOCKS 4096
#define NT 256
#define HH 1024
#define MASK_WORDS (32 * 32 * 1024)

__device__ uint32_t g_maskT[MASK_WORDS];   // [n][R][w], 4MB
__device__ uint32_t g_maskP[MASK_WORDS];
__device__ double   g_part_bce[A_BLOCKS];
__device__ unsigned long long g_tot, g_cnt;    // zero-init; reset by finisher
__device__ unsigned int g_counter;             // zero-init; reset by finisher

__device__ __forceinline__ float bce_term(float p, float t) {
    return fmaxf(p, 0.f) - p * t + __logf(1.f + __expf(-fabsf(p)));
}
// t in {0.0f,1.0f}: IEEE bit 23 is 1 for 1.0f and 0 for 0.0f.
__device__ __forceinline__ uint32_t tb_of(float t) {
    return (__float_as_uint(t) >> 23) & 1u;
}
// p > 0 <=> signed-int bit pattern > 0.
__device__ __forceinline__ uint32_t pb_of(float p) {
    return (uint32_t)((int)__float_as_uint(p) > 0);
}

__global__ void __launch_bounds__(NT)
stream_k(const float* __restrict__ preds, const float* __restrict__ targs) {
    const int tid = blockIdx.x * NT + threadIdx.x;
    const int c4 = tid & 255;            // 4-column group
    const int R  = (tid >> 8) & 31;      // 32-row word index
    const int n  = tid >> 13;

    const long base = ((long)n << 20) + ((long)(R << 5) << 10) + (c4 << 2);
    const float* pb = preds + base;
    const float* tb = targs + base;

    uint32_t twx = 0, twy = 0, twz = 0, tww = 0;
    uint32_t pwx = 0, pwy = 0, pwz = 0, pww = 0;
    float bce = 0.f;

    #pragma unroll
    for (int j8 = 0; j8 < 8; ++j8) {
        float4 P[4], T[4];
        #pragma unroll
        for (int k = 0; k < 4; ++k) {
            P[k] = __ldcs((const float4*)(pb + (((j8 << 2) + k) << 10)));
            T[k] = __ldcs((const float4*)(tb + (((j8 << 2) + k) << 10)));
        }
        #pragma unroll
        for (int k = 0; k < 4; ++k) {
            const int j = (j8 << 2) + k;
            bce += bce_term(P[k].x, T[k].x) + bce_term(P[k].y, T[k].y)
                 + bce_term(P[k].z, T[k].z) + bce_term(P[k].w, T[k].w);
            twx |= tb_of(T[k].x) << j;  pwx |= pb_of(P[k].x) << j;
            twy |= tb_of(T[k].y) << j;  pwy |= pb_of(P[k].y) << j;
            twz |= tb_of(T[k].z) << j;  pwz |= pb_of(P[k].z) << j;
            tww |= tb_of(T[k].w) << j;  pww |= pb_of(P[k].w) << j;
        }
    }

    const int midx = (((n << 5) + R) << 10) + (c4 << 2);
    *(uint4*)(g_maskT + midx) = make_uint4(twx, twy, twz, tww);
    *(uint4*)(g_maskP + midx) = make_uint4(pwx, pwy, pwz, pww);

    const unsigned fm = 0xFFFFFFFFu;
    for (int off = 16; off; off >>= 1) bce += __shfl_down_sync(fm, bce, off);
    __shared__ float rb[8];
    const int wid = threadIdx.x >> 5, lane = threadIdx.x & 31;
    if (lane == 0) rb[wid] = bce;
    __syncthreads();
    if (threadIdx.x == 0) {
        float b2 = 0.f;
        #pragma unroll
        for (int i = 0; i < 8; ++i) b2 += rb[i];
        g_part_bce[blockIdx.x] = (double)b2;
    }
}

__global__ void __launch_bounds__(NT)
dist_k(float* __restrict__ out) {
    // blockIdx = ((n*32 + R) * 4 + wc); column w = wc*256 + threadIdx.x
    const int wc = blockIdx.x & 3;
    const int R  = (blockIdx.x >> 2) & 31;
    const int n  = blockIdx.x >> 7;
    const int w  = (wc << 8) + threadIdx.x;

    const uint32_t* mt = g_maskT + ((n << 15) + w);   // word r at mt[r<<10]
    const uint32_t tw = mt[R << 10];
    const uint32_t pq = g_maskP[(n << 15) + (R << 10) + w] & ~tw;

    // bootstrap: last target strictly before this word (expected 1 probe)
    int ltv = -4096;
    for (int rr = R - 1; rr >= 0; --rr) {
        const uint32_t v = mt[rr << 10];
        if (v) { ltv = (rr << 5) + 31 - __clz(v); break; }
    }
    // bootstrap: first target strictly after this word
    int ntb = 8192;
    for (int rr = R + 1; rr < 32; ++rr) {
        const uint32_t v = mt[rr << 10];
        if (v) { ntb = (rr << 5) + __ffs(v) - 1; break; }
    }

    uint32_t tot = 0u;
    uint32_t cnt = (uint32_t)__popc(pq);
    const int h0 = R << 5;

    // iterate only set bits of pq (~8/word expected); iterations independent
    uint32_t m = pq;
    while (m) {
        const int b = __ffs(m) - 1;
        m &= m - 1u;
        const int h = h0 + b;
        const uint32_t tlow = tw & ((1u << b) - 1u);          // targets below b
        const int lt = tlow ? (h0 + 31 - __clz(tlow)) : ltv;
        const uint32_t thigh = tw >> b;                        // targets above b (bit b clear)
        const int nt = thigh ? (h + __ffs(thigh) - 1) : ntb;
        tot += (uint32_t)min(min(h - lt, nt - h), HH);
    }

    // integer warp+block reduce -> global atomics (order-independent)
    const unsigned fm = 0xFFFFFFFFu;
    for (int off = 16; off; off >>= 1) {
        tot += __shfl_down_sync(fm, tot, off);
        cnt += __shfl_down_sync(fm, cnt, off);
    }
    __shared__ uint32_t rt[8], rc[8];
    const int wid = threadIdx.x >> 5, lane = threadIdx.x & 31;
    if (lane == 0) { rt[wid] = tot; rc[wid] = cnt; }
    __syncthreads();
    __shared__ int s_last;
    if (threadIdx.x == 0) {
        uint32_t t2 = 0u, c2 = 0u;
        #pragma unroll
        for (int i = 0; i < 8; ++i) { t2 += rt[i]; c2 += rc[i]; }
        atomicAdd(&g_tot, (unsigned long long)t2);
        atomicAdd(&g_cnt, (unsigned long long)c2);
        __threadfence();
        const unsigned old = atomicAdd(&g_counter, 1u);
        s_last = (old == B_BLOCKS - 1);
    }
    __syncthreads();

    if (s_last) {
        __shared__ double fb[NT];
        double b = 0.0;
        #pragma unroll
        for (int i = 0; i < A_BLOCKS / NT; ++i)
            b += g_part_bce[threadIdx.x + NT * i];
        fb[threadIdx.x] = b;
        __syncthreads();
        for (int s = NT / 2; s; s >>= 1) {
            if (threadIdx.x < s) fb[threadIdx.x] += fb[threadIdx.x + s];
            __syncthreads();
        }
        if (threadIdx.x == 0) {
            const unsigned long long T = g_tot, C = g_cnt;
            const double bce_mean = fb[0] / 33554432.0;   // 32*1024*1024
            const double border = (T == 0ull) ? 0.0
                                 : (double)T / ((double)C < 1.0 ? 1.0 : (double)C);
            out[0] = (float)(bce_mean + sqrt(border));
            g_tot = 0ull; g_cnt = 0ull; g_counter = 0u;   // reset for next replay
        }
    }
}

extern "C" void kernel_launch(void* const* d_in, const int* in_sizes, int n_in,
                              void* d_out, int out_size) {
    const float* preds = (const float*)d_in[0];
    const float* targs = (const float*)d_in[1];
    stream_k<<<A_BLOCKS, NT>>>(preds, targs);
    dist_k<<<B_BLOCKS, NT>>>((float*)d_out);
}

// round 16
// speedup vs baseline: 1.9221x; 1.0878x over previous
#include <cuda_runtime.h>
#include <stdint.h>
#include <math.h>

// DistanceTransformLoss v5 (fused lean streamer + in-smem set-bit distance pass).
//
// out = mean(BCEWithLogits(pred,tgt)) + sqrt( sum(pred_bin*dist)/max(cnt,1) ), 0 if sum==0
// dist[h] = min(|h - nearest target along H|, H) per (n,w) column. Shapes (32,1,1024,1024) f32.
//
// 256 blocks (32 n x 8 tiles of 128 cols), 512 threads.
// Pass 1: warp g (0..15) streams rows [64g,64g+64); lane owns 4 adjacent cols via
//   float4 (8 LDG.128 batched in flight). BCE inline; target/pred bits packed to
//   smem per-column words ([col][33] padded layout, conflict-free).
// Pass 2 (after 1 barrier): thread = (col, 256-row segment). Backward-built fw[]
//   next-target table + forward lt — branchless except the set-bit loop over
//   pq bits (~64/thread). ALU work overlaps other blocks' HBM streaming.
// Ticketed deterministic finisher: integer atomics; fixed-order BCE fold; resets.

#define NBLK 256
#define NTH  512
#define HH 1024
#define MS 33                 // padded words per column

__device__ double   g_part_bce[NBLK];
__device__ unsigned long long g_tot, g_cnt;   // zero-init; reset by finisher
__device__ unsigned int g_counter;            // zero-init; reset by finisher

__device__ __forceinline__ float bce_term(float p, float t) {
    return fmaxf(p, 0.f) - p * t + __logf(1.f + __expf(-fabsf(p)));
}
// t in {0.0f,1.0f}: IEEE bit 23 is 1 for 1.0f, 0 for 0.0f.
__device__ __forceinline__ uint32_t tb_of(float t) {
    return (__float_as_uint(t) >> 23) & 1u;
}
// p > 0 <=> signed-int bit pattern > 0.
__device__ __forceinline__ uint32_t pb_of(float p) {
    return (uint32_t)((int)__float_as_uint(p) > 0);
}

__global__ void __launch_bounds__(NTH)
dtl_fused(const float* __restrict__ preds, const float* __restrict__ targs,
          float* __restrict__ out) {
    __shared__ uint32_t s_t[128 * MS];
    __shared__ uint32_t s_p[128 * MS];

    const int tid  = threadIdx.x;
    const int g    = tid >> 5;               // warp 0..15: rows [64g, 64g+64)
    const int lane = tid & 31;
    const int n    = blockIdx.x >> 3;
    const int w0   = (blockIdx.x & 7) << 7;  // tile * 128
    const int col0 = lane << 2;              // 4 cols per lane

    const long base = ((long)n << 20) + ((long)(g << 6) << 10) + w0 + col0;
    float bce = 0.f;

    // ---- Pass 1: stream 64 rows x 4 cols, BCE + bit packing into smem ----
    #pragma unroll
    for (int w4 = 0; w4 < 2; ++w4) {         // two 32-row words per warp
        uint32_t twx = 0, twy = 0, twz = 0, tww = 0;
        uint32_t pwx = 0, pwy = 0, pwz = 0, pww = 0;
        #pragma unroll
        for (int r8 = 0; r8 < 8; ++r8) {     // 4-row batches
            const long off = base + ((long)((w4 << 5) + (r8 << 2)) << 10);
            float4 P[4], T[4];
            #pragma unroll
            for (int k = 0; k < 4; ++k) {
                P[k] = __ldcs((const float4*)(preds + off + ((long)k << 10)));
                T[k] = __ldcs((const float4*)(targs + off + ((long)k << 10)));
            }
            #pragma unroll
            for (int k = 0; k < 4; ++k) {
                const int j = (r8 << 2) + k;
                bce += bce_term(P[k].x, T[k].x) + bce_term(P[k].y, T[k].y)
                     + bce_term(P[k].z, T[k].z) + bce_term(P[k].w, T[k].w);
                twx |= tb_of(T[k].x) << j;  pwx |= pb_of(P[k].x) << j;
                twy |= tb_of(T[k].y) << j;  pwy |= pb_of(P[k].y) << j;
                twz |= tb_of(T[k].z) << j;  pwz |= pb_of(P[k].z) << j;
                tww |= tb_of(T[k].w) << j;  pww |= pb_of(P[k].w) << j;
            }
        }
        const int word = (g << 1) + w4;
        s_t[(col0 + 0) * MS + word] = twx;  s_p[(col0 + 0) * MS + word] = pwx;
        s_t[(col0 + 1) * MS + word] = twy;  s_p[(col0 + 1) * MS + word] = pwy;
        s_t[(col0 + 2) * MS + word] = twz;  s_p[(col0 + 2) * MS + word] = pwz;
        s_t[(col0 + 3) * MS + word] = tww;  s_p[(col0 + 3) * MS + word] = pww;
    }
    __syncthreads();

    // ---- Pass 2: set-bit distance scan; thread = (col, 8-word segment) ----
    const int col = tid & 127;
    const int q   = tid >> 7;                // 0..3
    const uint32_t* Tm = s_t + col * MS;
    const uint32_t* Pm = s_p + col * MS;
    const int Rb = q << 3;

    // ltv: last target strictly before segment (expected 1 probe)
    int ltv = -4096;
    for (int rr = Rb - 1; rr >= 0; --rr) {
        const uint32_t v = Tm[rr];
        if (v) { ltv = (rr << 5) + 31 - __clz(v); break; }
    }
    // fw[wo]: first target at/after word Rb+wo; fw[8] = first after segment
    int fw[9];
    {
        int f = 8192;
        for (int rr = Rb + 8; rr < 32; ++rr) {
            const uint32_t v = Tm[rr];
            if (v) { f = (rr << 5) + __ffs(v) - 1; break; }
        }
        fw[8] = f;
        #pragma unroll
        for (int wo = 7; wo >= 0; --wo) {
            const uint32_t v = Tm[Rb + wo];
            fw[wo] = v ? (((Rb + wo) << 5) + __ffs(v) - 1) : fw[wo + 1];
        }
    }

    uint32_t tot = 0u, cnt = 0u;
    #pragma unroll
    for (int wo = 0; wo < 8; ++wo) {
        const uint32_t tw = Tm[Rb + wo];
        const uint32_t pq = Pm[Rb + wo] & ~tw;
        cnt += (uint32_t)__popc(pq);
        const int h0 = (Rb + wo) << 5;
        uint32_t m = pq;
        while (m) {
            const int b = __ffs(m) - 1;
            m &= m - 1u;
            const int h = h0 + b;
            const uint32_t tlow  = tw & ((1u << b) - 1u);
            const int lt = tlow ? (h0 + 31 - __clz(tlow)) : ltv;
            const uint32_t thigh = tw >> b;
            const int nt = thigh ? (h + __ffs(thigh) - 1) : fw[wo + 1];
            tot += (uint32_t)min(min(h - lt, nt - h), HH);
        }
        ltv = tw ? (h0 + 31 - __clz(tw)) : ltv;   // advance for next word
    }

    // ---- Block reduction ----
    const unsigned fm = 0xFFFFFFFFu;
    for (int off = 16; off; off >>= 1) {
        bce += __shfl_down_sync(fm, bce, off);
        tot += __shfl_down_sync(fm, tot, off);
        cnt += __shfl_down_sync(fm, cnt, off);
    }
    __shared__ float    rbce[16];
    __shared__ uint32_t rtot[16], rcnt[16];
    if (lane == 0) { rbce[g] = bce; rtot[g] = tot; rcnt[g] = cnt; }
    __syncthreads();
    __shared__ int s_last;
    if (tid == 0) {
        float    b2 = 0.f;
        uint32_t t2 = 0u, c2 = 0u;
        #pragma unroll
        for (int i = 0; i < 16; ++i) { b2 += rbce[i]; t2 += rtot[i]; c2 += rcnt[i]; }
        g_part_bce[blockIdx.x] = (double)b2;
        atomicAdd(&g_tot, (unsigned long long)t2);
        atomicAdd(&g_cnt, (unsigned long long)c2);
        __threadfence();
        const unsigned old = atomicAdd(&g_counter, 1u);
        s_last = (old == NBLK - 1);
    }
    __syncthreads();

    // ---- Ticketed last block: deterministic BCE fold + scalar write ----
    if (s_last) {
        __shared__ double fb[NBLK];
        if (tid < NBLK) fb[tid] = g_part_bce[tid];
        __syncthreads();
        for (int s = NBLK / 2; s; s >>= 1) {
            if (tid < s) fb[tid] += fb[tid + s];
            __syncthreads();
        }
        if (tid == 0) {
            const unsigned long long T = g_tot, C = g_cnt;
            const double bce_mean = fb[0] / 33554432.0;   // 32*1024*1024
            const double border = (T == 0ull) ? 0.0
                                 : (double)T / ((double)C < 1.0 ? 1.0 : (double)C);
            out[0] = (float)(bce_mean + sqrt(border));
            g_tot = 0ull; g_cnt = 0ull; g_counter = 0u;   // reset for next replay
        }
    }
}

extern "C" void kernel_launch(void* const* d_in, const int* in_sizes, int n_in,
                              void* d_out, int out_size) {
    const float* preds = (const float*)d_in[0];
    const float* targs = (const float*)d_in[1];
    dtl_fused<<<NBLK, NTH>>>(preds, targs, (float*)d_out);
}